// round 3
// baseline (speedup 1.0000x reference)
#include <cuda_runtime.h>
#include <cstdint>
#include <cstddef>

// SNN Leaky scan, warp-specialized, predicate-free recurrence.
//   reset_t = H(mem_{t-1} - 1);  mem_t = beta*mem_{t-1} + x_t - reset_t;  spk_t = H(mem_t - 1)
// Per-step SASS (all fixed-lat-4 ALU/FMA ops, NO predicates):
//   r   = FSET.GT(mem, 1.0)   // float 1.0/0.0, lat 4   (r == reset_t, and == spk_{t-1})
//   a   = FFMA(beta, mem, x)  // lat 4, parallel with FSET
//   mem = a - r               // FADD joins both at +4  -> period = 8 cyc/step
// spk_t is simply r computed after the update (same op as next step's reset).
//
// Warps 0-1: compute (thread t owns row t). Warps 2-3: all global I/O through a
// 3-buffer SMEM ring (cp.async 2 chunks ahead; coalesced float4 spike stores),
// overlapped with compute. XOR-swizzled tiles: conflict-free LDS/STS.128.

namespace {
constexpr int N_TOTAL  = 8192;
constexpr int T_STEPS  = 4000;
constexpr float BETA   = 0.95f;

constexpr int ROWS     = 64;     // rows per CTA
constexpr int CTHREADS = 64;     // compute threads (warps 0,1)
constexpr int THREADS  = 128;    // + io warps 2,3
constexpr int TCHUNK   = 128;    // time steps per chunk
constexpr int TC4      = TCHUNK / 4;                         // 32 float4 per row-chunk
constexpr int NCHUNK   = (T_STEPS + TCHUNK - 1) / TCHUNK;    // 32 (31 full + one 32-step tail)
constexpr int TAIL4    = (T_STEPS - (NCHUNK - 1) * TCHUNK) / 4;  // 8
constexpr int NBUF     = 3;
constexpr size_t SMEM_BYTES = (size_t)NBUF * ROWS * TC4 * sizeof(float4);  // 96 KB
}

__device__ __forceinline__ void cp_async16(void* sdst, const void* gsrc) {
    uint32_t s = (uint32_t)__cvta_generic_to_shared(sdst);
    asm volatile("cp.async.cg.shared.global [%0], [%1], 16;" :: "r"(s), "l"(gsrc));
}
__device__ __forceinline__ void cp_commit() {
    asm volatile("cp.async.commit_group;" ::: "memory");
}
template <int NN>
__device__ __forceinline__ void cp_wait() {
    asm volatile("cp.async.wait_group %0;" :: "n"(NN) : "memory");
}

// Heaviside as float via FSET (no FSETP/SEL, no predicate latency).
__device__ __forceinline__ float fset_gt1(float v) {
    float r;
    asm("set.gt.f32.f32 %0, %1, %2;" : "=f"(r) : "f"(v), "f"(1.0f));
    return r;
}

// One step. On entry r == reset_t (= spk_{t-1}); on exit r == spk_t.
__device__ __forceinline__ void snn_step(float& mem, float& r, float x, float& spk) {
    float a = __fmaf_rn(BETA, mem, x);
    mem = a - r;              // critical chain: FFMA(4) -> FADD(4) = 8 cyc
    r = fset_gt1(mem);        // off-chain for mem; feeds next step's FADD (ready in time)
    spk = r;
}

__global__ void __launch_bounds__(THREADS, 1)
snn_leaky_ws_kernel(const float* __restrict__ inp, float* __restrict__ out) {
    extern __shared__ float4 smem[];
    const int tid  = threadIdx.x;
    const int lane = tid & 31;
    const int rowBase = blockIdx.x * ROWS;
    const bool is_io = (tid >= CTHREADS);
    const int iow = (tid - CTHREADS) >> 5;   // 0 or 1 (io warps only)

    float4* buf[NBUF] = { smem, smem + ROWS * TC4, smem + 2 * ROWS * TC4 };

    // ---- prologue: io warps preload chunks 0 and 1 (one commit group each) ----
    if (is_io) {
        for (int c0 = 0; c0 < 2; ++c0) {
            for (int r = iow; r < ROWS; r += 2) {
                const float4* g = reinterpret_cast<const float4*>(
                    inp + (size_t)(rowBase + r) * T_STEPS + c0 * TCHUNK);
                cp_async16(&buf[c0][r * TC4 + (lane ^ (r & 31))], g + lane);
            }
            cp_commit();
        }
    }

    float mem = 0.0f, rst = 0.0f;   // mem_0-precursor = 0 => reset_0 = 0

    for (int c = 0; c <= NCHUNK; ++c) {
        if (is_io) cp_wait<1>();   // chunk c landed (<=1 group may remain in flight)
        __syncthreads();

        if (!is_io) {
            if (c < NCHUNK) {
                float4* rowp = buf[c % NBUF] + tid * TC4;
                const int sw = tid & 31;
                if (c != NCHUNK - 1) {
                    #pragma unroll
                    for (int t4 = 0; t4 < TC4; ++t4) {
                        float4 x = rowp[t4 ^ sw];     // conflict-free LDS.128
                        float4 s;
                        snn_step(mem, rst, x.x, s.x);
                        snn_step(mem, rst, x.y, s.y);
                        snn_step(mem, rst, x.z, s.z);
                        snn_step(mem, rst, x.w, s.w);
                        rowp[t4 ^ sw] = s;            // conflict-free STS.128
                    }
                } else {
                    #pragma unroll
                    for (int t4 = 0; t4 < TAIL4; ++t4) {
                        float4 x = rowp[t4 ^ sw];
                        float4 s;
                        snn_step(mem, rst, x.x, s.x);
                        snn_step(mem, rst, x.y, s.y);
                        snn_step(mem, rst, x.z, s.z);
                        snn_step(mem, rst, x.w, s.w);
                        rowp[t4 ^ sw] = s;
                    }
                }
            }
        } else {
            // ---- store spikes of chunk c-1 (coalesced float4) ----
            if (c >= 1) {
                const int cp = c - 1;
                const int nv4 = (cp == NCHUNK - 1) ? TAIL4 : TC4;
                float4* b = buf[cp % NBUF];
                for (int r = iow; r < ROWS; r += 2) {
                    if (lane < nv4) {
                        float4 v = b[r * TC4 + (lane ^ (r & 31))];
                        reinterpret_cast<float4*>(
                            out + (size_t)(rowBase + r) * T_STEPS + cp * TCHUNK)[lane] = v;
                    }
                }
            }
            // ---- prefetch chunk c+2 ----
            if (c + 2 < NCHUNK) {
                const int cn = c + 2;
                const int nv4 = (cn == NCHUNK - 1) ? TAIL4 : TC4;
                float4* b = buf[cn % NBUF];
                for (int r = iow; r < ROWS; r += 2) {
                    if (lane < nv4) {
                        const float4* g = reinterpret_cast<const float4*>(
                            inp + (size_t)(rowBase + r) * T_STEPS + cn * TCHUNK);
                        cp_async16(&b[r * TC4 + (lane ^ (r & 31))], g + lane);
                    }
                }
            }
            cp_commit();   // unconditional: uniform group counting across io threads
        }
    }
}

extern "C" void kernel_launch(void* const* d_in, const int* in_sizes, int n_in,
                              void* d_out, int out_size) {
    (void)in_sizes; (void)n_in; (void)out_size;
    const float* inp = (const float*)d_in[0];
    float* out = (float*)d_out;

    cudaFuncSetAttribute(snn_leaky_ws_kernel,
                         cudaFuncAttributeMaxDynamicSharedMemorySize,
                         (int)SMEM_BYTES);
    snn_leaky_ws_kernel<<<N_TOTAL / ROWS, THREADS, SMEM_BYTES>>>(inp, out);
}

// round 4
// speedup vs baseline: 1.0167x; 1.0167x over previous
#include <cuda_runtime.h>
#include <cstdint>
#include <cstddef>

// SNN Leaky scan, warp-specialized, separate in/out SMEM (no LDS/STS aliasing),
// software-pipelined LDS in the compute loop.
//   reset_t = H(mem_{t-1} - 1);  mem_t = beta*mem_{t-1} + x_t - reset_t;  spk_t = H(mem_t - 1)
//
// Warps 0-1: compute (thread t owns row t). Warps 2-3: all global I/O.
// Input ring: 3 buffers (cp.async, 2 chunks ahead). Output: 2 ping-pong buffers
// (compute STS -> io warps STG next chunk). XOR-swizzled tiles: conflict-free
// LDS/STS.128 everywhere. One __syncthreads per chunk.

namespace {
constexpr int N_TOTAL  = 8192;
constexpr int T_STEPS  = 4000;
constexpr float BETA   = 0.95f;

constexpr int ROWS     = 64;     // rows per CTA
constexpr int CTHREADS = 64;     // compute threads (warps 0,1)
constexpr int THREADS  = 128;    // + io warps 2,3
constexpr int TCHUNK   = 128;    // time steps per chunk
constexpr int TC4      = TCHUNK / 4;                          // 32 float4 per row-chunk
constexpr int NCHUNK   = (T_STEPS + TCHUNK - 1) / TCHUNK;     // 32 (31 full + 32-step tail)
constexpr int TAIL4    = (T_STEPS - (NCHUNK - 1) * TCHUNK) / 4;  // 8
constexpr int BUFELEM  = ROWS * TC4;                          // float4 per buffer
constexpr size_t SMEM_BYTES = (size_t)(3 + 2) * BUFELEM * sizeof(float4);  // 160 KB
}

__device__ __forceinline__ void cp_async16(void* sdst, const void* gsrc) {
    uint32_t s = (uint32_t)__cvta_generic_to_shared(sdst);
    asm volatile("cp.async.cg.shared.global [%0], [%1], 16;" :: "r"(s), "l"(gsrc));
}
__device__ __forceinline__ void cp_commit() {
    asm volatile("cp.async.commit_group;" ::: "memory");
}
template <int NN>
__device__ __forceinline__ void cp_wait() {
    asm volatile("cp.async.wait_group %0;" :: "n"(NN) : "memory");
}

// Heaviside as float (no branch; compiler may use FSET or FSETP+FSEL, both short).
__device__ __forceinline__ float fset_gt1(float v) {
    float r;
    asm("set.gt.f32.f32 %0, %1, %2;" : "=f"(r) : "f"(v), "f"(1.0f));
    return r;
}

// On entry r == reset_t (= spk_{t-1}); on exit r == spk_t.
__device__ __forceinline__ void snn_step(float& mem, float& r, float x, float& spk) {
    float a = __fmaf_rn(BETA, mem, x);
    mem = a - r;              // FFMA(4) -> FADD(4): 8-cyc mem chain
    r = fset_gt1(mem);
    spk = r;
}

__device__ __forceinline__ float4 snn_step4(float& mem, float& r, float4 x) {
    float4 s;
    snn_step(mem, r, x.x, s.x);
    snn_step(mem, r, x.y, s.y);
    snn_step(mem, r, x.z, s.z);
    snn_step(mem, r, x.w, s.w);
    return s;
}

__global__ void __launch_bounds__(THREADS, 1)
snn_leaky_ws_kernel(const float* __restrict__ inp, float* __restrict__ out) {
    extern __shared__ float4 smem[];
    const int tid  = threadIdx.x;
    const int lane = tid & 31;
    const int rowBase = blockIdx.x * ROWS;
    const bool is_io = (tid >= CTHREADS);
    const int iow = (tid - CTHREADS) >> 5;   // 0 or 1 (io warps only)

    float4* inbuf[3]  = { smem, smem + BUFELEM, smem + 2 * BUFELEM };
    float4* outbuf[2] = { smem + 3 * BUFELEM, smem + 4 * BUFELEM };

    // ---- prologue: io warps preload chunks 0 and 1 (one commit group each) ----
    if (is_io) {
        for (int c0 = 0; c0 < 2; ++c0) {
            for (int r = iow; r < ROWS; r += 2) {
                const float4* g = reinterpret_cast<const float4*>(
                    inp + (size_t)(rowBase + r) * T_STEPS + c0 * TCHUNK);
                cp_async16(&inbuf[c0][r * TC4 + (lane ^ (r & 31))], g + lane);
            }
            cp_commit();
        }
    }

    float mem = 0.0f, rst = 0.0f;

    for (int c = 0; c <= NCHUNK; ++c) {
        if (is_io) cp_wait<1>();   // input chunk c landed (<=1 group outstanding)
        __syncthreads();

        if (!is_io) {
            if (c < NCHUNK) {
                const float4* __restrict__ rin  = inbuf[c % 3] + tid * TC4;
                float4* __restrict__       rout = outbuf[c & 1] + tid * TC4;
                const int sw = tid & 31;
                if (c != NCHUNK - 1) {
                    // software pipeline: LDS issued 2 float4-iters ahead of use
                    float4 xa = rin[0 ^ sw];
                    float4 xb = rin[1 ^ sw];
                    #pragma unroll
                    for (int t4 = 0; t4 < TC4; ++t4) {
                        float4 xc;
                        if (t4 + 2 < TC4) xc = rin[(t4 + 2) ^ sw];
                        rout[t4 ^ sw] = snn_step4(mem, rst, xa);
                        xa = xb; xb = xc;
                    }
                } else {
                    float4 xa = rin[0 ^ sw];
                    float4 xb = rin[1 ^ sw];
                    #pragma unroll
                    for (int t4 = 0; t4 < TAIL4; ++t4) {
                        float4 xc;
                        if (t4 + 2 < TAIL4) xc = rin[(t4 + 2) ^ sw];
                        rout[t4 ^ sw] = snn_step4(mem, rst, xa);
                        xa = xb; xb = xc;
                    }
                }
            }
        } else {
            // ---- store spikes of chunk c-1 (coalesced float4) ----
            if (c >= 1) {
                const int cp = c - 1;
                const int nv4 = (cp == NCHUNK - 1) ? TAIL4 : TC4;
                const float4* b = outbuf[cp & 1];
                for (int r = iow; r < ROWS; r += 2) {
                    if (lane < nv4) {
                        float4 v = b[r * TC4 + (lane ^ (r & 31))];
                        reinterpret_cast<float4*>(
                            out + (size_t)(rowBase + r) * T_STEPS + cp * TCHUNK)[lane] = v;
                    }
                }
            }
            // ---- prefetch input chunk c+2 ----
            if (c + 2 < NCHUNK) {
                const int cn = c + 2;
                const int nv4 = (cn == NCHUNK - 1) ? TAIL4 : TC4;
                float4* b = inbuf[cn % 3];
                for (int r = iow; r < ROWS; r += 2) {
                    if (lane < nv4) {
                        const float4* g = reinterpret_cast<const float4*>(
                            inp + (size_t)(rowBase + r) * T_STEPS + cn * TCHUNK);
                        cp_async16(&b[r * TC4 + (lane ^ (r & 31))], g + lane);
                    }
                }
            }
            cp_commit();   // unconditional: uniform group counting
        }
    }
}

extern "C" void kernel_launch(void* const* d_in, const int* in_sizes, int n_in,
                              void* d_out, int out_size) {
    (void)in_sizes; (void)n_in; (void)out_size;
    const float* inp = (const float*)d_in[0];
    float* out = (float*)d_out;

    cudaFuncSetAttribute(snn_leaky_ws_kernel,
                         cudaFuncAttributeMaxDynamicSharedMemorySize,
                         (int)SMEM_BYTES);
    snn_leaky_ws_kernel<<<N_TOTAL / ROWS, THREADS, SMEM_BYTES>>>(inp, out);
}